// round 2
// baseline (speedup 1.0000x reference)
#include <cuda_runtime.h>
#include <math.h>

#define N_NODES 50000
#define N_EDGES 800000
#define N_GRAPHS 128
#define NEG_SLOPE 0.2f

// ---------------- scratch (device globals; no allocation allowed) ----------------
__device__ float g_z1[N_NODES * 96];
__device__ float g_el1[N_NODES * 3];
__device__ float g_er1[N_NODES * 3];
__device__ float g_max1[N_NODES * 3];
__device__ float g_sum1[N_NODES * 3];
__device__ float g_ex1[3 * N_EDGES];      // [h][e]
__device__ float g_x1[N_NODES * 96];      // layer-1 output (pre-relu accumulator)

__device__ float g_z2[N_NODES * 192];
__device__ float g_el2[N_NODES * 3];
__device__ float g_er2[N_NODES * 3];
__device__ float g_max2[N_NODES * 3];
__device__ float g_sum2[N_NODES * 3];
__device__ float g_ex2[3 * N_EDGES];      // [h][e]
__device__ float g_x2[N_NODES * 192];     // layer-2 output (pre-relu accumulator)

__device__ float g_pool[N_GRAPHS * 192];
__device__ float g_cnt[N_GRAPHS];

// ---------------- helpers ----------------
__device__ __forceinline__ void atomicMaxF(float* addr, float v) {
    // sign-split trick: exact float max without CAS loops
    if (v >= 0.0f) atomicMax((int*)addr, __float_as_int(v));
    else           atomicMin((unsigned int*)addr, __float_as_uint(v));
}

// ---------------- init (runs every replay; accumulators must be re-zeroed) ----------------
__global__ void k_init() {
    int i = blockIdx.x * blockDim.x + threadIdx.x;
    if (i < N_NODES * 96)  g_x1[i] = 0.0f;
    if (i < N_NODES * 192) g_x2[i] = 0.0f;
    if (i < N_NODES * 3) {
        g_sum1[i] = 0.0f; g_sum2[i] = 0.0f;
        g_max1[i] = -INFINITY; g_max2[i] = -INFINITY;
    }
    if (i < N_GRAPHS * 192) g_pool[i] = 0.0f;
    if (i < N_GRAPHS)       g_cnt[i] = 0.0f;
}

// ---------------- layer 1: z1 = feat @ W1, el1/er1 ----------------
__global__ void k_layer1_z(const float* __restrict__ feat, const float* __restrict__ W1,
                           const float* __restrict__ al1, const float* __restrict__ ar1) {
    int n = blockIdx.x * blockDim.x + threadIdx.x;
    if (n >= N_NODES) return;
    float f[10];
#pragma unroll
    for (int k = 0; k < 10; k++) f[k] = feat[n * 10 + k];
    float el[3] = {0.f, 0.f, 0.f}, er[3] = {0.f, 0.f, 0.f};
#pragma unroll 4
    for (int o = 0; o < 96; o++) {
        float acc = 0.f;
#pragma unroll
        for (int k = 0; k < 10; k++) acc = fmaf(f[k], __ldg(&W1[k * 96 + o]), acc);
        g_z1[n * 96 + o] = acc;
        int h = o >> 5, d = o & 31;
        el[h] = fmaf(acc, __ldg(&al1[h * 32 + d]), el[h]);
        er[h] = fmaf(acc, __ldg(&ar1[h * 32 + d]), er[h]);
    }
#pragma unroll
    for (int h = 0; h < 3; h++) { g_el1[n * 3 + h] = el[h]; g_er1[n * 3 + h] = er[h]; }
}

// ---------------- generic edge kernels (templated so device code resolves the
//                  __device__ globals; host code must NOT take their address) ----
// pass 1: e = leaky_relu(el[src] + er[dst]); store; atomic max per (dst, h)
template<int LAYER>
__global__ void k_edge_logits(const int* __restrict__ src, const int* __restrict__ dst) {
    const float* el    = (LAYER == 1) ? g_el1 : g_el2;
    const float* er    = (LAYER == 1) ? g_er1 : g_er2;
    float* estore      = (LAYER == 1) ? g_ex1 : g_ex2;
    float* nmax        = (LAYER == 1) ? g_max1 : g_max2;
    int i = blockIdx.x * blockDim.x + threadIdx.x;
    if (i >= 3 * N_EDGES) return;
    int h = i / N_EDGES;
    int e = i - h * N_EDGES;
    int s = src[e], d = dst[e];
    float v = el[s * 3 + h] + er[d * 3 + h];
    v = (v > 0.f) ? v : NEG_SLOPE * v;
    estore[i] = v;
    atomicMaxF(&nmax[d * 3 + h], v);
}

// pass 2: ex = exp(e - max[dst]); store; atomic sum per (dst, h)
template<int LAYER>
__global__ void k_edge_exp(const int* __restrict__ dst) {
    float* estore      = (LAYER == 1) ? g_ex1 : g_ex2;
    const float* nmax  = (LAYER == 1) ? g_max1 : g_max2;
    float* nsum        = (LAYER == 1) ? g_sum1 : g_sum2;
    int i = blockIdx.x * blockDim.x + threadIdx.x;
    if (i >= 3 * N_EDGES) return;
    int h = i / N_EDGES;
    int e = i - h * N_EDGES;
    int d = dst[e];
    float ex = expf(estore[i] - nmax[d * 3 + h]);
    estore[i] = ex;
    atomicAdd(&nsum[d * 3 + h], ex);
}

// ---------------- message passing, layer 1 (D=32): one warp per edge ----------------
__global__ void k_msg1(const int* __restrict__ src, const int* __restrict__ dst) {
    int gw = (blockIdx.x * blockDim.x + threadIdx.x) >> 5;
    int lane = threadIdx.x & 31;
    if (gw >= N_EDGES) return;
    int s = src[gw], d = dst[gw];
#pragma unroll
    for (int h = 0; h < 3; h++) {
        float a = g_ex1[h * N_EDGES + gw] / (g_sum1[d * 3 + h] + 1e-16f);
        int j = h * 32 + lane;
        atomicAdd(&g_x1[d * 96 + j], g_z1[s * 96 + j] * a);
    }
}

// ---------------- layer 2 GEMM: z2 = relu(x1) @ W2   [50000x96]@[96x192] ----------------
#define GT 8   // nodes per block
__global__ void k_layer2_z(const float* __restrict__ W2) {
    __shared__ float xs[96][GT];   // [k][i] so per-thread reads can vectorize
    int o = threadIdx.x;           // 0..191  output column
    int base = blockIdx.x * GT;
    for (int idx = threadIdx.x; idx < 96 * GT; idx += 192) {
        int i = idx / 96, k = idx - i * 96;
        int n = base + i;
        xs[k][i] = (n < N_NODES) ? fmaxf(g_x1[n * 96 + k], 0.f) : 0.f;
    }
    __syncthreads();
    float acc[GT];
#pragma unroll
    for (int i = 0; i < GT; i++) acc[i] = 0.f;
    for (int k = 0; k < 96; k++) {
        float w = __ldg(&W2[k * 192 + o]);
        float4 x0 = *reinterpret_cast<const float4*>(&xs[k][0]);
        float4 x1 = *reinterpret_cast<const float4*>(&xs[k][4]);
        acc[0] = fmaf(x0.x, w, acc[0]); acc[1] = fmaf(x0.y, w, acc[1]);
        acc[2] = fmaf(x0.z, w, acc[2]); acc[3] = fmaf(x0.w, w, acc[3]);
        acc[4] = fmaf(x1.x, w, acc[4]); acc[5] = fmaf(x1.y, w, acc[5]);
        acc[6] = fmaf(x1.z, w, acc[6]); acc[7] = fmaf(x1.w, w, acc[7]);
    }
#pragma unroll
    for (int i = 0; i < GT; i++) {
        int n = base + i;
        if (n < N_NODES) g_z2[n * 192 + o] = acc[i];
    }
}

// ---------------- layer 2 attention coefficients ----------------
__global__ void k_attn2(const float* __restrict__ al2, const float* __restrict__ ar2) {
    int i = blockIdx.x * blockDim.x + threadIdx.x;
    if (i >= N_NODES * 3) return;
    int n = i / 3, h = i - n * 3;
    float el = 0.f, er = 0.f;
#pragma unroll 8
    for (int d = 0; d < 64; d++) {
        float z = g_z2[n * 192 + h * 64 + d];
        el = fmaf(z, __ldg(&al2[h * 64 + d]), el);
        er = fmaf(z, __ldg(&ar2[h * 64 + d]), er);
    }
    g_el2[i] = el; g_er2[i] = er;
}

// ---------------- message passing, layer 2 (D=64): one warp per edge ----------------
__global__ void k_msg2(const int* __restrict__ src, const int* __restrict__ dst) {
    int gw = (blockIdx.x * blockDim.x + threadIdx.x) >> 5;
    int lane = threadIdx.x & 31;
    if (gw >= N_EDGES) return;
    int s = src[gw], d = dst[gw];
    float a[3];
#pragma unroll
    for (int h = 0; h < 3; h++)
        a[h] = g_ex2[h * N_EDGES + gw] / (g_sum2[d * 3 + h] + 1e-16f);
#pragma unroll
    for (int c = 0; c < 6; c++) {
        int j = c * 32 + lane;
        atomicAdd(&g_x2[d * 192 + j], g_z2[s * 192 + j] * a[c >> 1]);
    }
}

// ---------------- pooling ----------------
__global__ void k_pool(const int* __restrict__ gid) {
    int i = blockIdx.x * blockDim.x + threadIdx.x;
    if (i >= N_NODES * 192) return;
    int n = i / 192, j = i - n * 192;
    int g = gid[n];
    atomicAdd(&g_pool[g * 192 + j], fmaxf(g_x2[i], 0.f));
    if (j == 0) atomicAdd(&g_cnt[g], 1.0f);
}

// ---------------- final MLP: out[g] = relu(mean @ d1_w + d1_b) @ d2_w + d2_b ----------------
__global__ void k_mlp(const float* __restrict__ d1w, const float* __restrict__ d1b,
                      const float* __restrict__ d2w, const float* __restrict__ d2b,
                      float* __restrict__ out) {
    int g = blockIdx.x;
    int j = threadIdx.x;  // 0..63
    __shared__ float ps[192];
    __shared__ float hred[64];
    float inv = 1.0f / fmaxf(g_cnt[g], 1.0f);
    for (int k = j; k < 192; k += 64) ps[k] = g_pool[g * 192 + k] * inv;
    __syncthreads();
    float acc = d1b[j];
#pragma unroll 8
    for (int k = 0; k < 192; k++) acc = fmaf(ps[k], __ldg(&d1w[k * 64 + j]), acc);
    acc = fmaxf(acc, 0.f);
    hred[j] = acc * __ldg(&d2w[j]);
    __syncthreads();
    for (int s = 32; s > 0; s >>= 1) {
        if (j < s) hred[j] += hred[j + s];
        __syncthreads();
    }
    if (j == 0) out[g] = hred[0] + d2b[0];
}

// ---------------- launch ----------------
extern "C" void kernel_launch(void* const* d_in, const int* in_sizes, int n_in,
                              void* d_out, int out_size) {
    const float* feature = (const float*)d_in[0];
    const int*   src     = (const int*)d_in[1];
    const int*   dst     = (const int*)d_in[2];
    const int*   gid     = (const int*)d_in[3];
    const float* W1      = (const float*)d_in[4];
    const float* al1     = (const float*)d_in[5];
    const float* ar1     = (const float*)d_in[6];
    const float* W2      = (const float*)d_in[7];
    const float* al2     = (const float*)d_in[8];
    const float* ar2     = (const float*)d_in[9];
    const float* d1w     = (const float*)d_in[10];
    const float* d1b     = (const float*)d_in[11];
    const float* d2w     = (const float*)d_in[12];
    const float* d2b     = (const float*)d_in[13];
    float* out = (float*)d_out;

    // init accumulators (covers largest region: N_NODES*192 = 9.6M)
    {
        int total = N_NODES * 192;
        k_init<<<(total + 255) / 256, 256>>>();
    }
    // ---- layer 1 ----
    k_layer1_z<<<(N_NODES + 127) / 128, 128>>>(feature, W1, al1, ar1);
    {
        int total = 3 * N_EDGES;
        k_edge_logits<1><<<(total + 255) / 256, 256>>>(src, dst);
        k_edge_exp<1><<<(total + 255) / 256, 256>>>(dst);
    }
    {
        long long threads = (long long)N_EDGES * 32;
        k_msg1<<<(int)((threads + 255) / 256), 256>>>(src, dst);
    }
    // ---- layer 2 ----
    k_layer2_z<<<(N_NODES + GT - 1) / GT, 192>>>(W2);
    k_attn2<<<(N_NODES * 3 + 255) / 256, 256>>>(al2, ar2);
    {
        int total = 3 * N_EDGES;
        k_edge_logits<2><<<(total + 255) / 256, 256>>>(src, dst);
        k_edge_exp<2><<<(total + 255) / 256, 256>>>(dst);
    }
    {
        long long threads = (long long)N_EDGES * 32;
        k_msg2<<<(int)((threads + 255) / 256), 256>>>(src, dst);
    }
    // ---- pool + MLP ----
    {
        int total = N_NODES * 192;
        k_pool<<<(total + 255) / 256, 256>>>(gid);
    }
    k_mlp<<<N_GRAPHS, 64>>>(d1w, d1b, d2w, d2b, out);
}

// round 6
// speedup vs baseline: 1.2924x; 1.2924x over previous
#include <cuda_runtime.h>
#include <math.h>

#define N_NODES 50000
#define N_EDGES 800000
#define N_GRAPHS 128
#define NEG_SLOPE 0.2f

// ---------------- scratch (device globals; no allocation allowed) ----------------
__device__ float g_z1[N_NODES * 96];
__device__ float g_el1[N_NODES * 3];
__device__ float g_er1[N_NODES * 3];
__device__ float g_max1[N_NODES * 3];
__device__ float g_sum1[N_NODES * 3];
__device__ float g_ex1[3 * N_EDGES];      // [h][e] unnormalized exp
__device__ float g_x1[N_NODES * 96];      // layer-1 output (pre-relu)

__device__ float g_z2[N_NODES * 192];
__device__ float g_el2[N_NODES * 3];
__device__ float g_er2[N_NODES * 3];
__device__ float g_max2[N_NODES * 3];
__device__ float g_sum2[N_NODES * 3];
__device__ float g_ex2[3 * N_EDGES];      // [h][e]
__device__ float g_x2[N_NODES * 192];     // layer-2 output (pre-relu)

__device__ float g_pool[N_GRAPHS * 192];
__device__ float g_cnt[N_GRAPHS];

// CSR scratch (new this round)
__device__ int g_deg[N_NODES];
__device__ int g_off[N_NODES + 1];
__device__ int g_cur[N_NODES];
__device__ int g_esrc[N_EDGES];           // src node id at sorted position
__device__ int g_eid[N_EDGES];            // original edge id at sorted position

// ---------------- helpers ----------------
__device__ __forceinline__ void atomicMaxF(float* addr, float v) {
    if (v >= 0.0f) atomicMax((int*)addr, __float_as_int(v));
    else           atomicMin((unsigned int*)addr, __float_as_uint(v));
}

// ---------------- init (R2-proven form + deg zeroing) ----------------
__global__ void k_init() {
    int i = blockIdx.x * blockDim.x + threadIdx.x;
    if (i < N_NODES * 96)  g_x1[i] = 0.0f;
    if (i < N_NODES * 192) g_x2[i] = 0.0f;
    if (i < N_NODES * 3) {
        g_sum1[i] = 0.0f; g_sum2[i] = 0.0f;
        g_max1[i] = -INFINITY; g_max2[i] = -INFINITY;
    }
    if (i < N_NODES) g_deg[i] = 0;
    if (i < N_GRAPHS * 192) g_pool[i] = 0.0f;
    if (i < N_GRAPHS)       g_cnt[i] = 0.0f;
}

// ---------------- CSR build ----------------
__global__ void k_hist(const int* __restrict__ dst) {
    int e = blockIdx.x * blockDim.x + threadIdx.x;
    if (e < N_EDGES) atomicAdd(&g_deg[dst[e]], 1);
}

// single-block chunked exclusive scan (shared mem + syncthreads only)
#define SCAN_T 256
#define SCAN_CHUNK ((N_NODES + SCAN_T - 1) / SCAN_T)   // 196
__global__ void k_scan(const int* __restrict__ dst_unused) {
    __shared__ int psum[SCAN_T];
    int t = threadIdx.x;
    int lo = t * SCAN_CHUNK;
    int hi = (lo + SCAN_CHUNK < N_NODES) ? (lo + SCAN_CHUNK) : N_NODES;
    int s = 0;
    for (int n = lo; n < hi; n++) s += g_deg[n];
    psum[t] = s;
    __syncthreads();
    if (t == 0) {
        int run = 0;
        for (int i = 0; i < SCAN_T; i++) { int tmp = psum[i]; psum[i] = run; run += tmp; }
    }
    __syncthreads();
    int run = psum[t];
    for (int n = lo; n < hi; n++) {
        g_off[n] = run;
        g_cur[n] = run;
        run += g_deg[n];
    }
    if (t == 0) g_off[N_NODES] = N_EDGES;
}

__global__ void k_scatter(const int* __restrict__ src, const int* __restrict__ dst) {
    int e = blockIdx.x * blockDim.x + threadIdx.x;
    if (e < N_EDGES) {
        int p = atomicAdd(&g_cur[dst[e]], 1);
        g_esrc[p] = src[e];
        g_eid[p] = e;
    }
}

// ---------------- layer 1: z1 = feat @ W1, el1/er1 (R2 exact) ----------------
__global__ void k_layer1_z(const float* __restrict__ feat, const float* __restrict__ W1,
                           const float* __restrict__ al1, const float* __restrict__ ar1) {
    int n = blockIdx.x * blockDim.x + threadIdx.x;
    if (n >= N_NODES) return;
    float f[10];
#pragma unroll
    for (int k = 0; k < 10; k++) f[k] = feat[n * 10 + k];
    float el[3] = {0.f, 0.f, 0.f}, er[3] = {0.f, 0.f, 0.f};
#pragma unroll 4
    for (int o = 0; o < 96; o++) {
        float acc = 0.f;
#pragma unroll
        for (int k = 0; k < 10; k++) acc = fmaf(f[k], __ldg(&W1[k * 96 + o]), acc);
        g_z1[n * 96 + o] = acc;
        int h = o >> 5, d = o & 31;
        el[h] = fmaf(acc, __ldg(&al1[h * 32 + d]), el[h]);
        er[h] = fmaf(acc, __ldg(&ar1[h * 32 + d]), er[h]);
    }
#pragma unroll
    for (int h = 0; h < 3; h++) { g_el1[n * 3 + h] = el[h]; g_er1[n * 3 + h] = er[h]; }
}

// ---------------- edge softmax kernels (R2 exact, templated WITH args) ----------------
template<int LAYER>
__global__ void k_edge_logits(const int* __restrict__ src, const int* __restrict__ dst) {
    const float* el    = (LAYER == 1) ? g_el1 : g_el2;
    const float* er    = (LAYER == 1) ? g_er1 : g_er2;
    float* estore      = (LAYER == 1) ? g_ex1 : g_ex2;
    float* nmax        = (LAYER == 1) ? g_max1 : g_max2;
    int i = blockIdx.x * blockDim.x + threadIdx.x;
    if (i >= 3 * N_EDGES) return;
    int h = i / N_EDGES;
    int e = i - h * N_EDGES;
    int s = src[e], d = dst[e];
    float v = el[s * 3 + h] + er[d * 3 + h];
    v = (v > 0.f) ? v : NEG_SLOPE * v;
    estore[i] = v;
    atomicMaxF(&nmax[d * 3 + h], v);
}

template<int LAYER>
__global__ void k_edge_exp(const int* __restrict__ dst) {
    float* estore      = (LAYER == 1) ? g_ex1 : g_ex2;
    const float* nmax  = (LAYER == 1) ? g_max1 : g_max2;
    float* nsum        = (LAYER == 1) ? g_sum1 : g_sum2;
    int i = blockIdx.x * blockDim.x + threadIdx.x;
    if (i >= 3 * N_EDGES) return;
    int h = i / N_EDGES;
    int e = i - h * N_EDGES;
    int d = dst[e];
    float ex = expf(estore[i] - nmax[d * 3 + h]);
    estore[i] = ex;
    atomicAdd(&nsum[d * 3 + h], ex);
}

// ---------------- CSR gather message passing, layer 1 (D=32) ----------------
// warp per (node, head); no atomics; overwrites g_x1.
__global__ void k_msg1(const int* __restrict__ src, const int* __restrict__ dst) {
    int w = (blockIdx.x * blockDim.x + threadIdx.x) >> 5;
    if (w >= N_NODES * 3) return;
    int n = w / 3, h = w - n * 3;
    int lane = threadIdx.x & 31;
    int b0 = g_off[n], b1 = g_off[n + 1];
    float inv = 1.0f / (g_sum1[n * 3 + h] + 1e-16f);
    const float* exh = &g_ex1[h * N_EDGES];
    float acc = 0.f;
    for (int p = b0; p < b1; p++) {
        int sv = g_esrc[p];
        float a = exh[g_eid[p]];
        acc = fmaf(a, g_z1[sv * 96 + h * 32 + lane], acc);
    }
    g_x1[n * 96 + h * 32 + lane] = acc * inv;
}

// ---------------- layer 2 GEMM (R2 exact, relu on load) ----------------
#define GT 8   // nodes per block
__global__ void k_layer2_z(const float* __restrict__ W2) {
    __shared__ float xs[96][GT];
    int o = threadIdx.x;           // 0..191
    int base = blockIdx.x * GT;
    for (int idx = threadIdx.x; idx < 96 * GT; idx += 192) {
        int i = idx / 96, k = idx - i * 96;
        int n = base + i;
        xs[k][i] = (n < N_NODES) ? fmaxf(g_x1[n * 96 + k], 0.f) : 0.f;
    }
    __syncthreads();
    float acc[GT];
#pragma unroll
    for (int i = 0; i < GT; i++) acc[i] = 0.f;
    for (int k = 0; k < 96; k++) {
        float w = __ldg(&W2[k * 192 + o]);
        float4 x0 = *reinterpret_cast<const float4*>(&xs[k][0]);
        float4 x1 = *reinterpret_cast<const float4*>(&xs[k][4]);
        acc[0] = fmaf(x0.x, w, acc[0]); acc[1] = fmaf(x0.y, w, acc[1]);
        acc[2] = fmaf(x0.z, w, acc[2]); acc[3] = fmaf(x0.w, w, acc[3]);
        acc[4] = fmaf(x1.x, w, acc[4]); acc[5] = fmaf(x1.y, w, acc[5]);
        acc[6] = fmaf(x1.z, w, acc[6]); acc[7] = fmaf(x1.w, w, acc[7]);
    }
#pragma unroll
    for (int i = 0; i < GT; i++) {
        int n = base + i;
        if (n < N_NODES) g_z2[n * 192 + o] = acc[i];
    }
}

// ---------------- layer 2 attention coefficients (R2 exact) ----------------
__global__ void k_attn2(const float* __restrict__ al2, const float* __restrict__ ar2) {
    int i = blockIdx.x * blockDim.x + threadIdx.x;
    if (i >= N_NODES * 3) return;
    int n = i / 3, h = i - n * 3;
    float el = 0.f, er = 0.f;
#pragma unroll 8
    for (int d = 0; d < 64; d++) {
        float z = g_z2[n * 192 + h * 64 + d];
        el = fmaf(z, __ldg(&al2[h * 64 + d]), el);
        er = fmaf(z, __ldg(&ar2[h * 64 + d]), er);
    }
    g_el2[i] = el; g_er2[i] = er;
}

// ---------------- CSR gather message passing, layer 2 (D=64) ----------------
__global__ void k_msg2(const int* __restrict__ src, const int* __restrict__ dst) {
    int w = (blockIdx.x * blockDim.x + threadIdx.x) >> 5;
    if (w >= N_NODES * 3) return;
    int n = w / 3, h = w - n * 3;
    int lane = threadIdx.x & 31;
    int b0 = g_off[n], b1 = g_off[n + 1];
    float inv = 1.0f / (g_sum2[n * 3 + h] + 1e-16f);
    const float* exh = &g_ex2[h * N_EDGES];
    float acc0 = 0.f, acc1 = 0.f;
    for (int p = b0; p < b1; p++) {
        int sv = g_esrc[p];
        float a = exh[g_eid[p]];
        const float* zr = &g_z2[sv * 192 + h * 64];
        acc0 = fmaf(a, zr[lane], acc0);
        acc1 = fmaf(a, zr[lane + 32], acc1);
    }
    g_x2[n * 192 + h * 64 + lane]      = acc0 * inv;
    g_x2[n * 192 + h * 64 + lane + 32] = acc1 * inv;
}

// ---------------- pooling (R2 exact; relu applied here) ----------------
__global__ void k_pool(const int* __restrict__ gid) {
    int i = blockIdx.x * blockDim.x + threadIdx.x;
    if (i >= N_NODES * 192) return;
    int n = i / 192, j = i - n * 192;
    int g = gid[n];
    atomicAdd(&g_pool[g * 192 + j], fmaxf(g_x2[i], 0.f));
    if (j == 0) atomicAdd(&g_cnt[g], 1.0f);
}

// ---------------- final MLP (R2 exact) ----------------
__global__ void k_mlp(const float* __restrict__ d1w, const float* __restrict__ d1b,
                      const float* __restrict__ d2w, const float* __restrict__ d2b,
                      float* __restrict__ out) {
    int g = blockIdx.x;
    int j = threadIdx.x;  // 0..63
    __shared__ float ps[192];
    __shared__ float hred[64];
    float inv = 1.0f / fmaxf(g_cnt[g], 1.0f);
    for (int k = j; k < 192; k += 64) ps[k] = g_pool[g * 192 + k] * inv;
    __syncthreads();
    float acc = d1b[j];
#pragma unroll 8
    for (int k = 0; k < 192; k++) acc = fmaf(ps[k], __ldg(&d1w[k * 64 + j]), acc);
    acc = fmaxf(acc, 0.f);
    hred[j] = acc * __ldg(&d2w[j]);
    __syncthreads();
    for (int s = 32; s > 0; s >>= 1) {
        if (j < s) hred[j] += hred[j + s];
        __syncthreads();
    }
    if (j == 0) out[g] = hred[0] + d2b[0];
}

// ---------------- launch ----------------
extern "C" void kernel_launch(void* const* d_in, const int* in_sizes, int n_in,
                              void* d_out, int out_size) {
    const float* feature = (const float*)d_in[0];
    const int*   src     = (const int*)d_in[1];
    const int*   dst     = (const int*)d_in[2];
    const int*   gid     = (const int*)d_in[3];
    const float* W1      = (const float*)d_in[4];
    const float* al1     = (const float*)d_in[5];
    const float* ar1     = (const float*)d_in[6];
    const float* W2      = (const float*)d_in[7];
    const float* al2     = (const float*)d_in[8];
    const float* ar2     = (const float*)d_in[9];
    const float* d1w     = (const float*)d_in[10];
    const float* d1b     = (const float*)d_in[11];
    const float* d2w     = (const float*)d_in[12];
    const float* d2b     = (const float*)d_in[13];
    float* out = (float*)d_out;

    // init + CSR build (shared by both layers)
    k_init<<<(N_NODES * 192 + 255) / 256, 256>>>();
    k_hist<<<(N_EDGES + 255) / 256, 256>>>(dst);
    k_scan<<<1, SCAN_T>>>(dst);
    k_scatter<<<(N_EDGES + 255) / 256, 256>>>(src, dst);

    // ---- layer 1 ----
    k_layer1_z<<<(N_NODES + 127) / 128, 128>>>(feature, W1, al1, ar1);
    {
        int total = 3 * N_EDGES;
        k_edge_logits<1><<<(total + 255) / 256, 256>>>(src, dst);
        k_edge_exp<1><<<(total + 255) / 256, 256>>>(dst);
    }
    k_msg1<<<(N_NODES * 3 * 32 + 255) / 256, 256>>>(src, dst);

    // ---- layer 2 ----
    k_layer2_z<<<(N_NODES + GT - 1) / GT, 192>>>(W2);
    k_attn2<<<(N_NODES * 3 + 255) / 256, 256>>>(al2, ar2);
    {
        int total = 3 * N_EDGES;
        k_edge_logits<2><<<(total + 255) / 256, 256>>>(src, dst);
        k_edge_exp<2><<<(total + 255) / 256, 256>>>(dst);
    }
    k_msg2<<<(N_NODES * 3 * 32 + 255) / 256, 256>>>(src, dst);

    // ---- pool + MLP ----
    k_pool<<<(N_NODES * 192 + 255) / 256, 256>>>(gid);
    k_mlp<<<N_GRAPHS, 64>>>(d1w, d1b, d2w, d2b, out);
}

// round 8
// speedup vs baseline: 1.3957x; 1.0799x over previous
#include <cuda_runtime.h>
#include <math.h>

#define N_NODES 50000
#define N_EDGES 800000
#define N_GRAPHS 128
#define NEG_SLOPE 0.2f

// ---------------- scratch (device globals; no allocation allowed) ----------------
__device__ float g_z1[N_NODES * 96];
__device__ float g_el1[N_NODES * 3];
__device__ float g_er1[N_NODES * 3];
__device__ float g_x1[N_NODES * 96];      // layer-1 output (pre-relu)

__device__ float g_z2[N_NODES * 192];
__device__ float g_el2[N_NODES * 3];
__device__ float g_er2[N_NODES * 3];
__device__ float g_x2[N_NODES * 192];     // layer-2 output (pre-relu)

__device__ float g_pool[N_GRAPHS * 192];
__device__ float g_cnt[N_GRAPHS];

// CSR scratch
__device__ int g_deg[N_NODES];
__device__ int g_off[N_NODES + 1];
__device__ int g_cur[N_NODES];
__device__ int g_esrc[N_EDGES];           // src node id at dst-sorted position

// ---------------- init (must cover N_NODES for g_deg!) ----------------
__global__ void k_init(const int* __restrict__ dummy) {
    int i = blockIdx.x * blockDim.x + threadIdx.x;
    if (i < N_NODES) g_deg[i] = 0;
    if (i < N_GRAPHS * 192) g_pool[i] = 0.0f;
    if (i < N_GRAPHS)       g_cnt[i] = 0.0f;
}

// ---------------- CSR build (R6-proven) ----------------
__global__ void k_hist(const int* __restrict__ dst) {
    int e = blockIdx.x * blockDim.x + threadIdx.x;
    if (e < N_EDGES) atomicAdd(&g_deg[dst[e]], 1);
}

#define SCAN_T 256
#define SCAN_CHUNK ((N_NODES + SCAN_T - 1) / SCAN_T)   // 196
__global__ void k_scan(const int* __restrict__ dst_unused) {
    __shared__ int psum[SCAN_T];
    int t = threadIdx.x;
    int lo = t * SCAN_CHUNK;
    int hi = (lo + SCAN_CHUNK < N_NODES) ? (lo + SCAN_CHUNK) : N_NODES;
    int s = 0;
    for (int n = lo; n < hi; n++) s += g_deg[n];
    psum[t] = s;
    __syncthreads();
    if (t == 0) {
        int run = 0;
        for (int i = 0; i < SCAN_T; i++) { int tmp = psum[i]; psum[i] = run; run += tmp; }
    }
    __syncthreads();
    int run = psum[t];
    for (int n = lo; n < hi; n++) {
        g_off[n] = run;
        g_cur[n] = run;
        run += g_deg[n];
    }
    if (t == 0) g_off[N_NODES] = N_EDGES;
}

__global__ void k_scatter(const int* __restrict__ src, const int* __restrict__ dst) {
    int e = blockIdx.x * blockDim.x + threadIdx.x;
    if (e < N_EDGES) {
        int p = atomicAdd(&g_cur[dst[e]], 1);
        g_esrc[p] = src[e];
    }
}

// per-graph node counts
__global__ void k_cnt(const int* __restrict__ gid) {
    int n = blockIdx.x * blockDim.x + threadIdx.x;
    if (n < N_NODES) atomicAdd(&g_cnt[gid[n]], 1.0f);
}

// ---------------- layer 1: z1 = feat @ W1, el1/er1 (proven) ----------------
__global__ void k_layer1_z(const float* __restrict__ feat, const float* __restrict__ W1,
                           const float* __restrict__ al1, const float* __restrict__ ar1) {
    int n = blockIdx.x * blockDim.x + threadIdx.x;
    if (n >= N_NODES) return;
    float f[10];
#pragma unroll
    for (int k = 0; k < 10; k++) f[k] = feat[n * 10 + k];
    float el[3] = {0.f, 0.f, 0.f}, er[3] = {0.f, 0.f, 0.f};
#pragma unroll 4
    for (int o = 0; o < 96; o++) {
        float acc = 0.f;
#pragma unroll
        for (int k = 0; k < 10; k++) acc = fmaf(f[k], __ldg(&W1[k * 96 + o]), acc);
        g_z1[n * 96 + o] = acc;
        int h = o >> 5, d = o & 31;
        el[h] = fmaf(acc, __ldg(&al1[h * 32 + d]), el[h]);
        er[h] = fmaf(acc, __ldg(&ar1[h * 32 + d]), er[h]);
    }
#pragma unroll
    for (int h = 0; h < 3; h++) { g_el1[n * 3 + h] = el[h]; g_er1[n * 3 + h] = er[h]; }
}

// ---------------- fused online-softmax + aggregation, layer 1 (D=32) ----------------
// warp per (node, head). All lanes see identical (broadcast) esrc/el values, so
// the max/sum state is warp-uniform; each lane owns one feature dim of z.
__global__ void k_fused1(const int* __restrict__ src, const int* __restrict__ dst) {
    int w = (blockIdx.x * blockDim.x + threadIdx.x) >> 5;
    if (w >= N_NODES * 3) return;
    int n = w / 3, h = w - n * 3;
    int lane = threadIdx.x & 31;
    int b0 = g_off[n], b1 = g_off[n + 1];
    float ern = g_er1[n * 3 + h];
    float m = -INFINITY, s = 0.f, acc = 0.f;
    for (int p = b0; p < b1; p++) {
        int sv = g_esrc[p];
        float v = g_el1[sv * 3 + h] + ern;
        v = (v > 0.f) ? v : NEG_SLOPE * v;
        if (v > m) {
            float sc = expf(m - v);   // exp(-inf)=0 on first edge
            s *= sc; acc *= sc; m = v;
        }
        float e = expf(v - m);
        s += e;
        acc = fmaf(e, g_z1[sv * 96 + h * 32 + lane], acc);
    }
    float inv = 1.0f / (s + 1e-16f);
    g_x1[n * 96 + h * 32 + lane] = acc * inv;
}

// ---------------- layer 2 GEMM (proven, relu on load) ----------------
#define GT 8   // nodes per block
__global__ void k_layer2_z(const float* __restrict__ W2) {
    __shared__ float xs[96][GT];
    int o = threadIdx.x;           // 0..191
    int base = blockIdx.x * GT;
    for (int idx = threadIdx.x; idx < 96 * GT; idx += 192) {
        int i = idx / 96, k = idx - i * 96;
        int n = base + i;
        xs[k][i] = (n < N_NODES) ? fmaxf(g_x1[n * 96 + k], 0.f) : 0.f;
    }
    __syncthreads();
    float acc[GT];
#pragma unroll
    for (int i = 0; i < GT; i++) acc[i] = 0.f;
    for (int k = 0; k < 96; k++) {
        float w = __ldg(&W2[k * 192 + o]);
        float4 x0 = *reinterpret_cast<const float4*>(&xs[k][0]);
        float4 x1 = *reinterpret_cast<const float4*>(&xs[k][4]);
        acc[0] = fmaf(x0.x, w, acc[0]); acc[1] = fmaf(x0.y, w, acc[1]);
        acc[2] = fmaf(x0.z, w, acc[2]); acc[3] = fmaf(x0.w, w, acc[3]);
        acc[4] = fmaf(x1.x, w, acc[4]); acc[5] = fmaf(x1.y, w, acc[5]);
        acc[6] = fmaf(x1.z, w, acc[6]); acc[7] = fmaf(x1.w, w, acc[7]);
    }
#pragma unroll
    for (int i = 0; i < GT; i++) {
        int n = base + i;
        if (n < N_NODES) g_z2[n * 192 + o] = acc[i];
    }
}

// ---------------- layer 2 attention coefficients (proven) ----------------
__global__ void k_attn2(const float* __restrict__ al2, const float* __restrict__ ar2) {
    int i = blockIdx.x * blockDim.x + threadIdx.x;
    if (i >= N_NODES * 3) return;
    int n = i / 3, h = i - n * 3;
    float el = 0.f, er = 0.f;
#pragma unroll 8
    for (int d = 0; d < 64; d++) {
        float z = g_z2[n * 192 + h * 64 + d];
        el = fmaf(z, __ldg(&al2[h * 64 + d]), el);
        er = fmaf(z, __ldg(&ar2[h * 64 + d]), er);
    }
    g_el2[i] = el; g_er2[i] = er;
}

// ---------------- fused online-softmax + aggregation, layer 2 (D=64) ----------------
__global__ void k_fused2(const int* __restrict__ src, const int* __restrict__ dst) {
    int w = (blockIdx.x * blockDim.x + threadIdx.x) >> 5;
    if (w >= N_NODES * 3) return;
    int n = w / 3, h = w - n * 3;
    int lane = threadIdx.x & 31;
    int b0 = g_off[n], b1 = g_off[n + 1];
    float ern = g_er2[n * 3 + h];
    float m = -INFINITY, s = 0.f, acc0 = 0.f, acc1 = 0.f;
    for (int p = b0; p < b1; p++) {
        int sv = g_esrc[p];
        float v = g_el2[sv * 3 + h] + ern;
        v = (v > 0.f) ? v : NEG_SLOPE * v;
        if (v > m) {
            float sc = expf(m - v);
            s *= sc; acc0 *= sc; acc1 *= sc; m = v;
        }
        float e = expf(v - m);
        s += e;
        const float* zr = &g_z2[sv * 192 + h * 64];
        acc0 = fmaf(e, zr[lane], acc0);
        acc1 = fmaf(e, zr[lane + 32], acc1);
    }
    float inv = 1.0f / (s + 1e-16f);
    g_x2[n * 192 + h * 64 + lane]      = acc0 * inv;
    g_x2[n * 192 + h * 64 + lane + 32] = acc1 * inv;
}

// ---------------- pooling: 4 sorted-gid nodes per thread, run-merged atomics ----
#define PNP 4
__global__ void k_pool(const int* __restrict__ gid) {
    int t = blockIdx.x * blockDim.x + threadIdx.x;
    int groups = (N_NODES + PNP - 1) / PNP;        // 12500
    if (t >= groups * 192) return;
    int gidx = t / 192, j = t - gidx * 192;
    int n0 = gidx * PNP;
    int n1 = (n0 + PNP < N_NODES) ? (n0 + PNP) : N_NODES;
    float acc = 0.f;
    int cur = gid[n0];
    for (int n = n0; n < n1; n++) {
        int g = gid[n];
        if (g != cur) {
            atomicAdd(&g_pool[cur * 192 + j], acc);
            acc = 0.f; cur = g;
        }
        acc += fmaxf(g_x2[n * 192 + j], 0.f);      // relu applied here
    }
    atomicAdd(&g_pool[cur * 192 + j], acc);
}

// ---------------- final MLP (proven) ----------------
__global__ void k_mlp(const float* __restrict__ d1w, const float* __restrict__ d1b,
                      const float* __restrict__ d2w, const float* __restrict__ d2b,
                      float* __restrict__ out) {
    int g = blockIdx.x;
    int j = threadIdx.x;  // 0..63
    __shared__ float ps[192];
    __shared__ float hred[64];
    float inv = 1.0f / fmaxf(g_cnt[g], 1.0f);
    for (int k = j; k < 192; k += 64) ps[k] = g_pool[g * 192 + k] * inv;
    __syncthreads();
    float acc = d1b[j];
#pragma unroll 8
    for (int k = 0; k < 192; k++) acc = fmaf(ps[k], __ldg(&d1w[k * 64 + j]), acc);
    acc = fmaxf(acc, 0.f);
    hred[j] = acc * __ldg(&d2w[j]);
    __syncthreads();
    for (int s = 32; s > 0; s >>= 1) {
        if (j < s) hred[j] += hred[j + s];
        __syncthreads();
    }
    if (j == 0) out[g] = hred[0] + d2b[0];
}

// ---------------- launch ----------------
extern "C" void kernel_launch(void* const* d_in, const int* in_sizes, int n_in,
                              void* d_out, int out_size) {
    const float* feature = (const float*)d_in[0];
    const int*   src     = (const int*)d_in[1];
    const int*   dst     = (const int*)d_in[2];
    const int*   gid     = (const int*)d_in[3];
    const float* W1      = (const float*)d_in[4];
    const float* al1     = (const float*)d_in[5];
    const float* ar1     = (const float*)d_in[6];
    const float* W2      = (const float*)d_in[7];
    const float* al2     = (const float*)d_in[8];
    const float* ar2     = (const float*)d_in[9];
    const float* d1w     = (const float*)d_in[10];
    const float* d1b     = (const float*)d_in[11];
    const float* d2w     = (const float*)d_in[12];
    const float* d2b     = (const float*)d_in[13];
    float* out = (float*)d_out;

    // init + CSR build (init must cover N_NODES — g_deg is the largest range)
    k_init<<<(N_NODES + 255) / 256, 256>>>(dst);
    k_hist<<<(N_EDGES + 255) / 256, 256>>>(dst);
    k_scan<<<1, SCAN_T>>>(dst);
    k_scatter<<<(N_EDGES + 255) / 256, 256>>>(src, dst);
    k_cnt<<<(N_NODES + 255) / 256, 256>>>(gid);

    // ---- layer 1 ----
    k_layer1_z<<<(N_NODES + 127) / 128, 128>>>(feature, W1, al1, ar1);
    k_fused1<<<(N_NODES * 3 * 32 + 255) / 256, 256>>>(src, dst);

    // ---- layer 2 ----
    k_layer2_z<<<(N_NODES + GT - 1) / GT, 192>>>(W2);
    k_attn2<<<(N_NODES * 3 + 255) / 256, 256>>>(al2, ar2);
    k_fused2<<<(N_NODES * 3 * 32 + 255) / 256, 256>>>(src, dst);

    // ---- pool + MLP ----
    {
        int groups = (N_NODES + PNP - 1) / PNP;
        k_pool<<<(groups * 192 + 255) / 256, 256>>>(gid);
    }
    k_mlp<<<N_GRAPHS, 64>>>(d1w, d1b, d2w, d2b, out);
}

// round 9
// speedup vs baseline: 1.4642x; 1.0491x over previous
#include <cuda_runtime.h>
#include <math.h>

#define N_NODES 50000
#define N_EDGES 800000
#define N_GRAPHS 128
#define NEG_SLOPE 0.2f

// ---------------- scratch (device globals; no allocation allowed) ----------------
__device__ float g_z1[N_NODES * 96];
__device__ float g_el1[N_NODES * 3];
__device__ float g_er1[N_NODES * 3];
__device__ float g_x1[N_NODES * 96];

__device__ float g_z2[N_NODES * 192];
__device__ float g_el2[N_NODES * 3];
__device__ float g_er2[N_NODES * 3];
__device__ float g_x2[N_NODES * 192];

__device__ float g_a[3 * N_EDGES];        // leaky logits, then used as exp source  [h][sorted p]
__device__ float g_max[N_NODES * 3];      // per (node,head) max logit

__device__ float g_pool[N_GRAPHS * 192];
__device__ float g_cnt[N_GRAPHS];

// CSR scratch
__device__ int g_deg[N_NODES];
__device__ int g_off[N_NODES + 1];
__device__ int g_cur[N_NODES];
__device__ int g_esrc[N_EDGES];           // src node id at dst-sorted position
__device__ int g_edst[N_EDGES];           // dst node id at dst-sorted position

// ---------------- init (covers N_NODES*3 for g_max) ----------------
__global__ void k_init(const int* __restrict__ dummy) {
    int i = blockIdx.x * blockDim.x + threadIdx.x;
    if (i < N_NODES) g_deg[i] = 0;
    if (i < N_NODES * 3) g_max[i] = -INFINITY;
    if (i < N_GRAPHS * 192) g_pool[i] = 0.0f;
    if (i < N_GRAPHS)       g_cnt[i] = 0.0f;
}

// ---------------- CSR build (proven) ----------------
__global__ void k_hist(const int* __restrict__ dst) {
    int e = blockIdx.x * blockDim.x + threadIdx.x;
    if (e < N_EDGES) atomicAdd(&g_deg[dst[e]], 1);
}

#define SCAN_T 256
#define SCAN_CHUNK ((N_NODES + SCAN_T - 1) / SCAN_T)   // 196
__global__ void k_scan(const int* __restrict__ dst_unused) {
    __shared__ int psum[SCAN_T];
    int t = threadIdx.x;
    int lo = t * SCAN_CHUNK;
    int hi = (lo + SCAN_CHUNK < N_NODES) ? (lo + SCAN_CHUNK) : N_NODES;
    int s = 0;
    for (int n = lo; n < hi; n++) s += g_deg[n];
    psum[t] = s;
    __syncthreads();
    if (t == 0) {
        int run = 0;
        for (int i = 0; i < SCAN_T; i++) { int tmp = psum[i]; psum[i] = run; run += tmp; }
    }
    __syncthreads();
    int run = psum[t];
    for (int n = lo; n < hi; n++) {
        g_off[n] = run;
        g_cur[n] = run;
        run += g_deg[n];
    }
    if (t == 0) g_off[N_NODES] = N_EDGES;
}

__global__ void k_scatter(const int* __restrict__ src, const int* __restrict__ dst) {
    int e = blockIdx.x * blockDim.x + threadIdx.x;
    if (e < N_EDGES) {
        int d = dst[e];
        int p = atomicAdd(&g_cur[d], 1);
        g_esrc[p] = src[e];
        g_edst[p] = d;
    }
}

__global__ void k_cnt(const int* __restrict__ gid) {
    int n = blockIdx.x * blockDim.x + threadIdx.x;
    if (n < N_NODES) atomicAdd(&g_cnt[gid[n]], 1.0f);
}

// ---------------- helpers ----------------
__device__ __forceinline__ void atomicMaxF(float* addr, float v) {
    if (v >= 0.0f) atomicMax((int*)addr, __float_as_int(v));
    else           atomicMin((unsigned int*)addr, __float_as_uint(v));
}

// ---------------- layer 1: z1 = feat @ W1, el1/er1 (proven) ----------------
__global__ void k_layer1_z(const float* __restrict__ feat, const float* __restrict__ W1,
                           const float* __restrict__ al1, const float* __restrict__ ar1) {
    int n = blockIdx.x * blockDim.x + threadIdx.x;
    if (n >= N_NODES) return;
    float f[10];
#pragma unroll
    for (int k = 0; k < 10; k++) f[k] = feat[n * 10 + k];
    float el[3] = {0.f, 0.f, 0.f}, er[3] = {0.f, 0.f, 0.f};
#pragma unroll 4
    for (int o = 0; o < 96; o++) {
        float acc = 0.f;
#pragma unroll
        for (int k = 0; k < 10; k++) acc = fmaf(f[k], __ldg(&W1[k * 96 + o]), acc);
        g_z1[n * 96 + o] = acc;
        int h = o >> 5, d = o & 31;
        el[h] = fmaf(acc, __ldg(&al1[h * 32 + d]), el[h]);
        er[h] = fmaf(acc, __ldg(&ar1[h * 32 + d]), er[h]);
    }
#pragma unroll
    for (int h = 0; h < 3; h++) { g_el1[n * 3 + h] = el[h]; g_er1[n * 3 + h] = er[h]; }
}

// ---------------- logits: edge-parallel, coalesced store + atomic max ----------------
// layer selected via pointer args (non-template rule kept: real args present)
__global__ void k_logits(const float* __restrict__ el, const float* __restrict__ er) {
    int i = blockIdx.x * blockDim.x + threadIdx.x;
    if (i >= 3 * N_EDGES) return;
    int h = i / N_EDGES;
    int p = i - h * N_EDGES;
    int sv = g_esrc[p], dv = g_edst[p];
    float v = el[sv * 3 + h] + er[dv * 3 + h];
    v = (v > 0.f) ? v : NEG_SLOPE * v;
    g_a[i] = v;
    atomicMaxF(&g_max[dv * 3 + h], v);
}

// ---------------- aggregation layer 1 (D=32): warp per (node, head) ----------------
// max known -> single pass, no rescale branch; a[] and esrc[] are linear loads.
__global__ void k_agg1(const int* __restrict__ dummy) {
    int w = (blockIdx.x * blockDim.x + threadIdx.x) >> 5;
    if (w >= N_NODES * 3) return;
    int n = w / 3, h = w - n * 3;
    int lane = threadIdx.x & 31;
    int b0 = g_off[n], b1 = g_off[n + 1];
    float m = g_max[n * 3 + h];
    const float* ah = &g_a[h * N_EDGES];
    float s = 0.f, acc = 0.f;
    for (int p = b0; p < b1; p++) {
        float e = expf(ah[p] - m);
        int sv = g_esrc[p];
        s += e;
        acc = fmaf(e, g_z1[sv * 96 + h * 32 + lane], acc);
    }
    g_x1[n * 96 + h * 32 + lane] = acc / (s + 1e-16f);
}

// ---------------- layer 2 GEMM (proven, relu on load) ----------------
#define GT 8
__global__ void k_layer2_z(const float* __restrict__ W2) {
    __shared__ float xs[96][GT];
    int o = threadIdx.x;           // 0..191
    int base = blockIdx.x * GT;
    for (int idx = threadIdx.x; idx < 96 * GT; idx += 192) {
        int i = idx / 96, k = idx - i * 96;
        int n = base + i;
        xs[k][i] = (n < N_NODES) ? fmaxf(g_x1[n * 96 + k], 0.f) : 0.f;
    }
    __syncthreads();
    float acc[GT];
#pragma unroll
    for (int i = 0; i < GT; i++) acc[i] = 0.f;
    for (int k = 0; k < 96; k++) {
        float w = __ldg(&W2[k * 192 + o]);
        float4 x0 = *reinterpret_cast<const float4*>(&xs[k][0]);
        float4 x1 = *reinterpret_cast<const float4*>(&xs[k][4]);
        acc[0] = fmaf(x0.x, w, acc[0]); acc[1] = fmaf(x0.y, w, acc[1]);
        acc[2] = fmaf(x0.z, w, acc[2]); acc[3] = fmaf(x0.w, w, acc[3]);
        acc[4] = fmaf(x1.x, w, acc[4]); acc[5] = fmaf(x1.y, w, acc[5]);
        acc[6] = fmaf(x1.z, w, acc[6]); acc[7] = fmaf(x1.w, w, acc[7]);
    }
#pragma unroll
    for (int i = 0; i < GT; i++) {
        int n = base + i;
        if (n < N_NODES) g_z2[n * 192 + o] = acc[i];
    }
}

// ---------------- layer 2 attention coefficients (proven) ----------------
__global__ void k_attn2(const float* __restrict__ al2, const float* __restrict__ ar2) {
    int i = blockIdx.x * blockDim.x + threadIdx.x;
    if (i >= N_NODES * 3) return;
    int n = i / 3, h = i - n * 3;
    float el = 0.f, er = 0.f;
#pragma unroll 8
    for (int d = 0; d < 64; d++) {
        float z = g_z2[n * 192 + h * 64 + d];
        el = fmaf(z, __ldg(&al2[h * 64 + d]), el);
        er = fmaf(z, __ldg(&ar2[h * 64 + d]), er);
    }
    g_el2[i] = el; g_er2[i] = er;
}

// re-init g_max between layers
__global__ void k_remax(const int* __restrict__ dummy) {
    int i = blockIdx.x * blockDim.x + threadIdx.x;
    if (i < N_NODES * 3) g_max[i] = -INFINITY;
}

// ---------------- aggregation layer 2 (D=64): warp per (node, head) ----------------
__global__ void k_agg2(const int* __restrict__ dummy) {
    int w = (blockIdx.x * blockDim.x + threadIdx.x) >> 5;
    if (w >= N_NODES * 3) return;
    int n = w / 3, h = w - n * 3;
    int lane = threadIdx.x & 31;
    int b0 = g_off[n], b1 = g_off[n + 1];
    float m = g_max[n * 3 + h];
    const float* ah = &g_a[h * N_EDGES];
    float s = 0.f, acc0 = 0.f, acc1 = 0.f;
    for (int p = b0; p < b1; p++) {
        float e = expf(ah[p] - m);
        int sv = g_esrc[p];
        s += e;
        const float* zr = &g_z2[sv * 192 + h * 64];
        acc0 = fmaf(e, zr[lane], acc0);
        acc1 = fmaf(e, zr[lane + 32], acc1);
    }
    float inv = 1.0f / (s + 1e-16f);
    g_x2[n * 192 + h * 64 + lane]      = acc0 * inv;
    g_x2[n * 192 + h * 64 + lane + 32] = acc1 * inv;
}

// ---------------- pooling: run-merged atomics over sorted gid ----------------
#define PNP 4
__global__ void k_pool(const int* __restrict__ gid) {
    int t = blockIdx.x * blockDim.x + threadIdx.x;
    int groups = (N_NODES + PNP - 1) / PNP;        // 12500
    if (t >= groups * 192) return;
    int gidx = t / 192, j = t - gidx * 192;
    int n0 = gidx * PNP;
    int n1 = (n0 + PNP < N_NODES) ? (n0 + PNP) : N_NODES;
    float acc = 0.f;
    int cur = gid[n0];
    for (int n = n0; n < n1; n++) {
        int g = gid[n];
        if (g != cur) {
            atomicAdd(&g_pool[cur * 192 + j], acc);
            acc = 0.f; cur = g;
        }
        acc += fmaxf(g_x2[n * 192 + j], 0.f);      // relu applied here
    }
    atomicAdd(&g_pool[cur * 192 + j], acc);
}

// ---------------- final MLP (proven) ----------------
__global__ void k_mlp(const float* __restrict__ d1w, const float* __restrict__ d1b,
                      const float* __restrict__ d2w, const float* __restrict__ d2b,
                      float* __restrict__ out) {
    int g = blockIdx.x;
    int j = threadIdx.x;  // 0..63
    __shared__ float ps[192];
    __shared__ float hred[64];
    float inv = 1.0f / fmaxf(g_cnt[g], 1.0f);
    for (int k = j; k < 192; k += 64) ps[k] = g_pool[g * 192 + k] * inv;
    __syncthreads();
    float acc = d1b[j];
#pragma unroll 8
    for (int k = 0; k < 192; k++) acc = fmaf(ps[k], __ldg(&d1w[k * 64 + j]), acc);
    acc = fmaxf(acc, 0.f);
    hred[j] = acc * __ldg(&d2w[j]);
    __syncthreads();
    for (int s = 32; s > 0; s >>= 1) {
        if (j < s) hred[j] += hred[j + s];
        __syncthreads();
    }
    if (j == 0) out[g] = hred[0] + d2b[0];
}

// ---------------- launch ----------------
extern "C" void kernel_launch(void* const* d_in, const int* in_sizes, int n_in,
                              void* d_out, int out_size) {
    const float* feature = (const float*)d_in[0];
    const int*   src     = (const int*)d_in[1];
    const int*   dst     = (const int*)d_in[2];
    const int*   gid     = (const int*)d_in[3];
    const float* W1      = (const float*)d_in[4];
    const float* al1     = (const float*)d_in[5];
    const float* ar1     = (const float*)d_in[6];
    const float* W2      = (const float*)d_in[7];
    const float* al2     = (const float*)d_in[8];
    const float* ar2     = (const float*)d_in[9];
    const float* d1w     = (const float*)d_in[10];
    const float* d1b     = (const float*)d_in[11];
    const float* d2w     = (const float*)d_in[12];
    const float* d2b     = (const float*)d_in[13];
    float* out = (float*)d_out;

    // init + CSR build (init covers N_NODES*3 for g_max)
    k_init<<<(N_NODES * 3 + 255) / 256, 256>>>(dst);
    k_hist<<<(N_EDGES + 255) / 256, 256>>>(dst);
    k_scan<<<1, SCAN_T>>>(dst);
    k_scatter<<<(N_EDGES + 255) / 256, 256>>>(src, dst);
    k_cnt<<<(N_NODES + 255) / 256, 256>>>(gid);

    // ---- layer 1 ----
    k_layer1_z<<<(N_NODES + 127) / 128, 128>>>(feature, W1, al1, ar1);
    {
        // device-global pointers resolved inside device code; pass layer via el/er:
        // use wrapper kernels reading g_el1/g_er1 directly is not possible from host,
        // so k_logits takes raw pointers obtained ON DEVICE — instead we give it
        // the harness-independent trick: small copy kernels are overkill; simply
        // launch a layer-specific shim.
    }
    // shims below select layer by passing the device arrays through kernel args is
    // not possible from host; use two tiny wrapper kernels instead:
    // (defined via k_logits with pointers to input-layer el/er living in device
    //  globals — we instead specialize by duplicating the launch with pointer
    //  parameters taken from __device__ symbols is illegal host-side, so:)
    extern __global__ void k_logits1(const int*, const int*);
    extern __global__ void k_logits2(const int*, const int*);
    k_logits1<<<(3 * N_EDGES + 255) / 256, 256>>>(src, dst);
    k_agg1<<<(N_NODES * 3 * 32 + 255) / 256, 256>>>(src);

    // ---- layer 2 ----
    k_layer2_z<<<(N_NODES + GT - 1) / GT, 192>>>(W2);
    k_attn2<<<(N_NODES * 3 + 255) / 256, 256>>>(al2, ar2);
    k_remax<<<(N_NODES * 3 + 255) / 256, 256>>>(dst);
    k_logits2<<<(3 * N_EDGES + 255) / 256, 256>>>(src, dst);
    k_agg2<<<(N_NODES * 3 * 32 + 255) / 256, 256>>>(src);

    // ---- pool + MLP ----
    {
        int groups = (N_NODES + PNP - 1) / PNP;
        k_pool<<<(groups * 192 + 255) / 256, 256>>>(gid);
    }
    k_mlp<<<N_GRAPHS, 64>>>(d1w, d1b, d2w, d2b, out);
}

// layer-specific logits kernels (resolve device globals in device code; real args)
__global__ void k_logits1(const int* __restrict__ a, const int* __restrict__ b) {
    int i = blockIdx.x * blockDim.x + threadIdx.x;
    if (i >= 3 * N_EDGES) return;
    int h = i / N_EDGES;
    int p = i - h * N_EDGES;
    int sv = g_esrc[p], dv = g_edst[p];
    float v = g_el1[sv * 3 + h] + g_er1[dv * 3 + h];
    v = (v > 0.f) ? v : NEG_SLOPE * v;
    g_a[i] = v;
    atomicMaxF(&g_max[dv * 3 + h], v);
}

__global__ void k_logits2(const int* __restrict__ a, const int* __restrict__ b) {
    int i = blockIdx.x * blockDim.x + threadIdx.x;
    if (i >= 3 * N_EDGES) return;
    int h = i / N_EDGES;
    int p = i - h * N_EDGES;
    int sv = g_esrc[p], dv = g_edst[p];
    float v = g_el2[sv * 3 + h] + g_er2[dv * 3 + h];
    v = (v > 0.f) ? v : NEG_SLOPE * v;
    g_a[i] = v;
    atomicMaxF(&g_max[dv * 3 + h], v);
}

// round 10
// speedup vs baseline: 1.5286x; 1.0440x over previous
#include <cuda_runtime.h>
#include <math.h>

#define N_NODES 50000
#define N_EDGES 800000
#define N_GRAPHS 128
#define NEG_SLOPE 0.2f

// ---------------- scratch (device globals; no allocation allowed) ----------------
__device__ float g_z1[N_NODES * 96];
__device__ float g_el1[N_NODES * 3];
__device__ float g_er1[N_NODES * 3];
__device__ float g_x1[N_NODES * 96];

__device__ float g_z2[N_NODES * 192];
__device__ float g_el2[N_NODES * 3];
__device__ float g_er2[N_NODES * 3];
__device__ float g_x2[N_NODES * 192];

__device__ float g_a[3 * N_EDGES];        // leaky logits [h][sorted p]
__device__ float g_max[N_NODES * 3];      // per (node,head) max logit

__device__ float g_pool[N_GRAPHS * 192];
__device__ float g_cnt[N_GRAPHS];

// CSR scratch
__device__ int g_deg[N_NODES];
__device__ int g_off[N_NODES + 1];
__device__ int g_cur[N_NODES];
__device__ int g_esrc[N_EDGES];           // src node id at dst-sorted position
__device__ int g_edst[N_EDGES];           // dst node id at dst-sorted position

// ---------------- init (covers N_NODES*3 for g_max) ----------------
__global__ void k_init(const int* __restrict__ dummy) {
    int i = blockIdx.x * blockDim.x + threadIdx.x;
    if (i < N_NODES) g_deg[i] = 0;
    if (i < N_NODES * 3) g_max[i] = -INFINITY;
    if (i < N_GRAPHS * 192) g_pool[i] = 0.0f;
    if (i < N_GRAPHS)       g_cnt[i] = 0.0f;
}

// ---------------- CSR build (proven) ----------------
__global__ void k_hist(const int* __restrict__ dst) {
    int e = blockIdx.x * blockDim.x + threadIdx.x;
    if (e < N_EDGES) atomicAdd(&g_deg[dst[e]], 1);
}

#define SCAN_T 256
#define SCAN_CHUNK ((N_NODES + SCAN_T - 1) / SCAN_T)   // 196
__global__ void k_scan(const int* __restrict__ dst_unused) {
    __shared__ int psum[SCAN_T];
    int t = threadIdx.x;
    int lo = t * SCAN_CHUNK;
    int hi = (lo + SCAN_CHUNK < N_NODES) ? (lo + SCAN_CHUNK) : N_NODES;
    int s = 0;
    for (int n = lo; n < hi; n++) s += g_deg[n];
    psum[t] = s;
    __syncthreads();
    if (t == 0) {
        int run = 0;
        for (int i = 0; i < SCAN_T; i++) { int tmp = psum[i]; psum[i] = run; run += tmp; }
    }
    __syncthreads();
    int run = psum[t];
    for (int n = lo; n < hi; n++) {
        g_off[n] = run;
        g_cur[n] = run;
        run += g_deg[n];
    }
    if (t == 0) g_off[N_NODES] = N_EDGES;
}

__global__ void k_scatter(const int* __restrict__ src, const int* __restrict__ dst) {
    int e = blockIdx.x * blockDim.x + threadIdx.x;
    if (e < N_EDGES) {
        int d = dst[e];
        int p = atomicAdd(&g_cur[d], 1);
        g_esrc[p] = src[e];
        g_edst[p] = d;
    }
}

__global__ void k_cnt(const int* __restrict__ gid) {
    int n = blockIdx.x * blockDim.x + threadIdx.x;
    if (n < N_NODES) atomicAdd(&g_cnt[gid[n]], 1.0f);
}

// ---------------- helpers ----------------
__device__ __forceinline__ void atomicMaxF(float* addr, float v) {
    if (v >= 0.0f) atomicMax((int*)addr, __float_as_int(v));
    else           atomicMin((unsigned int*)addr, __float_as_uint(v));
}

// ---------------- layer 1: z1 = feat @ W1, el1/er1 (proven) ----------------
__global__ void k_layer1_z(const float* __restrict__ feat, const float* __restrict__ W1,
                           const float* __restrict__ al1, const float* __restrict__ ar1) {
    int n = blockIdx.x * blockDim.x + threadIdx.x;
    if (n >= N_NODES) return;
    float f[10];
#pragma unroll
    for (int k = 0; k < 10; k++) f[k] = feat[n * 10 + k];
    float el[3] = {0.f, 0.f, 0.f}, er[3] = {0.f, 0.f, 0.f};
#pragma unroll 4
    for (int o = 0; o < 96; o++) {
        float acc = 0.f;
#pragma unroll
        for (int k = 0; k < 10; k++) acc = fmaf(f[k], __ldg(&W1[k * 96 + o]), acc);
        g_z1[n * 96 + o] = acc;
        int h = o >> 5, d = o & 31;
        el[h] = fmaf(acc, __ldg(&al1[h * 32 + d]), el[h]);
        er[h] = fmaf(acc, __ldg(&ar1[h * 32 + d]), er[h]);
    }
#pragma unroll
    for (int h = 0; h < 3; h++) { g_el1[n * 3 + h] = el[h]; g_er1[n * 3 + h] = er[h]; }
}

// ---------------- logits: thread per sorted edge, all 3 heads ----------------
__global__ void k_logits1(const int* __restrict__ a, const int* __restrict__ b) {
    int p = blockIdx.x * blockDim.x + threadIdx.x;
    if (p >= N_EDGES) return;
    int sv = g_esrc[p], dv = g_edst[p];
    float v0 = g_el1[sv * 3 + 0] + g_er1[dv * 3 + 0];
    float v1 = g_el1[sv * 3 + 1] + g_er1[dv * 3 + 1];
    float v2 = g_el1[sv * 3 + 2] + g_er1[dv * 3 + 2];
    v0 = (v0 > 0.f) ? v0 : NEG_SLOPE * v0;
    v1 = (v1 > 0.f) ? v1 : NEG_SLOPE * v1;
    v2 = (v2 > 0.f) ? v2 : NEG_SLOPE * v2;
    g_a[p]               = v0;
    g_a[N_EDGES + p]     = v1;
    g_a[2 * N_EDGES + p] = v2;
    atomicMaxF(&g_max[dv * 3 + 0], v0);
    atomicMaxF(&g_max[dv * 3 + 1], v1);
    atomicMaxF(&g_max[dv * 3 + 2], v2);
}

__global__ void k_logits2(const int* __restrict__ a, const int* __restrict__ b) {
    int p = blockIdx.x * blockDim.x + threadIdx.x;
    if (p >= N_EDGES) return;
    int sv = g_esrc[p], dv = g_edst[p];
    float v0 = g_el2[sv * 3 + 0] + g_er2[dv * 3 + 0];
    float v1 = g_el2[sv * 3 + 1] + g_er2[dv * 3 + 1];
    float v2 = g_el2[sv * 3 + 2] + g_er2[dv * 3 + 2];
    v0 = (v0 > 0.f) ? v0 : NEG_SLOPE * v0;
    v1 = (v1 > 0.f) ? v1 : NEG_SLOPE * v1;
    v2 = (v2 > 0.f) ? v2 : NEG_SLOPE * v2;
    g_a[p]               = v0;
    g_a[N_EDGES + p]     = v1;
    g_a[2 * N_EDGES + p] = v2;
    atomicMaxF(&g_max[dv * 3 + 0], v0);
    atomicMaxF(&g_max[dv * 3 + 1], v1);
    atomicMaxF(&g_max[dv * 3 + 2], v2);
}

// ---------------- aggregation layer 1: warp per NODE, all 3 heads ----------------
// lane owns dim (h*32+lane) for h=0..2 -> 3 independent z-loads per edge + unroll.
__global__ void k_agg1(const int* __restrict__ dummy) {
    int n = (blockIdx.x * blockDim.x + threadIdx.x) >> 5;
    if (n >= N_NODES) return;
    int lane = threadIdx.x & 31;
    int b0 = g_off[n], b1 = g_off[n + 1];
    float m0 = g_max[n * 3 + 0], m1 = g_max[n * 3 + 1], m2 = g_max[n * 3 + 2];
    float s0 = 0.f, s1 = 0.f, s2 = 0.f;
    float a0 = 0.f, a1 = 0.f, a2 = 0.f;
#pragma unroll 2
    for (int p = b0; p < b1; p++) {
        int sv = g_esrc[p];
        float e0 = expf(g_a[p] - m0);
        float e1 = expf(g_a[N_EDGES + p] - m1);
        float e2 = expf(g_a[2 * N_EDGES + p] - m2);
        const float* zr = &g_z1[sv * 96];
        a0 = fmaf(e0, zr[lane], a0);
        a1 = fmaf(e1, zr[lane + 32], a1);
        a2 = fmaf(e2, zr[lane + 64], a2);
        s0 += e0; s1 += e1; s2 += e2;
    }
    g_x1[n * 96 + lane]      = a0 / (s0 + 1e-16f);
    g_x1[n * 96 + lane + 32] = a1 / (s1 + 1e-16f);
    g_x1[n * 96 + lane + 64] = a2 / (s2 + 1e-16f);
}

// ---------------- layer 2 GEMM (proven, relu on load) ----------------
#define GT 8
__global__ void k_layer2_z(const float* __restrict__ W2) {
    __shared__ float xs[96][GT];
    int o = threadIdx.x;           // 0..191
    int base = blockIdx.x * GT;
    for (int idx = threadIdx.x; idx < 96 * GT; idx += 192) {
        int i = idx / 96, k = idx - i * 96;
        int n = base + i;
        xs[k][i] = (n < N_NODES) ? fmaxf(g_x1[n * 96 + k], 0.f) : 0.f;
    }
    __syncthreads();
    float acc[GT];
#pragma unroll
    for (int i = 0; i < GT; i++) acc[i] = 0.f;
    for (int k = 0; k < 96; k++) {
        float w = __ldg(&W2[k * 192 + o]);
        float4 x0 = *reinterpret_cast<const float4*>(&xs[k][0]);
        float4 x1 = *reinterpret_cast<const float4*>(&xs[k][4]);
        acc[0] = fmaf(x0.x, w, acc[0]); acc[1] = fmaf(x0.y, w, acc[1]);
        acc[2] = fmaf(x0.z, w, acc[2]); acc[3] = fmaf(x0.w, w, acc[3]);
        acc[4] = fmaf(x1.x, w, acc[4]); acc[5] = fmaf(x1.y, w, acc[5]);
        acc[6] = fmaf(x1.z, w, acc[6]); acc[7] = fmaf(x1.w, w, acc[7]);
    }
#pragma unroll
    for (int i = 0; i < GT; i++) {
        int n = base + i;
        if (n < N_NODES) g_z2[n * 192 + o] = acc[i];
    }
}

// ---------------- layer 2 attention coefficients (proven) ----------------
__global__ void k_attn2(const float* __restrict__ al2, const float* __restrict__ ar2) {
    int i = blockIdx.x * blockDim.x + threadIdx.x;
    if (i >= N_NODES * 3) return;
    int n = i / 3, h = i - n * 3;
    float el = 0.f, er = 0.f;
#pragma unroll 8
    for (int d = 0; d < 64; d++) {
        float z = g_z2[n * 192 + h * 64 + d];
        el = fmaf(z, __ldg(&al2[h * 64 + d]), el);
        er = fmaf(z, __ldg(&ar2[h * 64 + d]), er);
    }
    g_el2[i] = el; g_er2[i] = er;
}

// re-init g_max between layers
__global__ void k_remax(const int* __restrict__ dummy) {
    int i = blockIdx.x * blockDim.x + threadIdx.x;
    if (i < N_NODES * 3) g_max[i] = -INFINITY;
}

// ---------------- aggregation layer 2: warp per NODE, all 3 heads (6 dims/lane) ----
__global__ void k_agg2(const int* __restrict__ dummy) {
    int n = (blockIdx.x * blockDim.x + threadIdx.x) >> 5;
    if (n >= N_NODES) return;
    int lane = threadIdx.x & 31;
    int b0 = g_off[n], b1 = g_off[n + 1];
    float m0 = g_max[n * 3 + 0], m1 = g_max[n * 3 + 1], m2 = g_max[n * 3 + 2];
    float s0 = 0.f, s1 = 0.f, s2 = 0.f;
    float a0 = 0.f, a1 = 0.f, a2 = 0.f, a3 = 0.f, a4 = 0.f, a5 = 0.f;
#pragma unroll 2
    for (int p = b0; p < b1; p++) {
        int sv = g_esrc[p];
        float e0 = expf(g_a[p] - m0);
        float e1 = expf(g_a[N_EDGES + p] - m1);
        float e2 = expf(g_a[2 * N_EDGES + p] - m2);
        const float* zr = &g_z2[sv * 192];
        a0 = fmaf(e0, zr[lane], a0);
        a1 = fmaf(e0, zr[lane + 32], a1);
        a2 = fmaf(e1, zr[lane + 64], a2);
        a3 = fmaf(e1, zr[lane + 96], a3);
        a4 = fmaf(e2, zr[lane + 128], a4);
        a5 = fmaf(e2, zr[lane + 160], a5);
        s0 += e0; s1 += e1; s2 += e2;
    }
    float i0 = 1.0f / (s0 + 1e-16f);
    float i1 = 1.0f / (s1 + 1e-16f);
    float i2 = 1.0f / (s2 + 1e-16f);
    g_x2[n * 192 + lane]       = a0 * i0;
    g_x2[n * 192 + lane + 32]  = a1 * i0;
    g_x2[n * 192 + lane + 64]  = a2 * i1;
    g_x2[n * 192 + lane + 96]  = a3 * i1;
    g_x2[n * 192 + lane + 128] = a4 * i2;
    g_x2[n * 192 + lane + 160] = a5 * i2;
}

// ---------------- pooling: run-merged atomics over sorted gid ----------------
#define PNP 4
__global__ void k_pool(const int* __restrict__ gid) {
    int t = blockIdx.x * blockDim.x + threadIdx.x;
    int groups = (N_NODES + PNP - 1) / PNP;        // 12500
    if (t >= groups * 192) return;
    int gidx = t / 192, j = t - gidx * 192;
    int n0 = gidx * PNP;
    int n1 = (n0 + PNP < N_NODES) ? (n0 + PNP) : N_NODES;
    float acc = 0.f;
    int cur = gid[n0];
    for (int n = n0; n < n1; n++) {
        int g = gid[n];
        if (g != cur) {
            atomicAdd(&g_pool[cur * 192 + j], acc);
            acc = 0.f; cur = g;
        }
        acc += fmaxf(g_x2[n * 192 + j], 0.f);      // relu applied here
    }
    atomicAdd(&g_pool[cur * 192 + j], acc);
}

// ---------------- final MLP (proven) ----------------
__global__ void k_mlp(const float* __restrict__ d1w, const float* __restrict__ d1b,
                      const float* __restrict__ d2w, const float* __restrict__ d2b,
                      float* __restrict__ out) {
    int g = blockIdx.x;
    int j = threadIdx.x;  // 0..63
    __shared__ float ps[192];
    __shared__ float hred[64];
    float inv = 1.0f / fmaxf(g_cnt[g], 1.0f);
    for (int k = j; k < 192; k += 64) ps[k] = g_pool[g * 192 + k] * inv;
    __syncthreads();
    float acc = d1b[j];
#pragma unroll 8
    for (int k = 0; k < 192; k++) acc = fmaf(ps[k], __ldg(&d1w[k * 64 + j]), acc);
    acc = fmaxf(acc, 0.f);
    hred[j] = acc * __ldg(&d2w[j]);
    __syncthreads();
    for (int s = 32; s > 0; s >>= 1) {
        if (j < s) hred[j] += hred[j + s];
        __syncthreads();
    }
    if (j == 0) out[g] = hred[0] + d2b[0];
}

// ---------------- launch ----------------
extern "C" void kernel_launch(void* const* d_in, const int* in_sizes, int n_in,
                              void* d_out, int out_size) {
    const float* feature = (const float*)d_in[0];
    const int*   src     = (const int*)d_in[1];
    const int*   dst     = (const int*)d_in[2];
    const int*   gid     = (const int*)d_in[3];
    const float* W1      = (const float*)d_in[4];
    const float* al1     = (const float*)d_in[5];
    const float* ar1     = (const float*)d_in[6];
    const float* W2      = (const float*)d_in[7];
    const float* al2     = (const float*)d_in[8];
    const float* ar2     = (const float*)d_in[9];
    const float* d1w     = (const float*)d_in[10];
    const float* d1b     = (const float*)d_in[11];
    const float* d2w     = (const float*)d_in[12];
    const float* d2b     = (const float*)d_in[13];
    float* out = (float*)d_out;

    // init + CSR build
    k_init<<<(N_NODES * 3 + 255) / 256, 256>>>(dst);
    k_hist<<<(N_EDGES + 255) / 256, 256>>>(dst);
    k_scan<<<1, SCAN_T>>>(dst);
    k_scatter<<<(N_EDGES + 255) / 256, 256>>>(src, dst);
    k_cnt<<<(N_NODES + 255) / 256, 256>>>(gid);

    // ---- layer 1 ----
    k_layer1_z<<<(N_NODES + 127) / 128, 128>>>(feature, W1, al1, ar1);
    k_logits1<<<(N_EDGES + 255) / 256, 256>>>(src, dst);
    k_agg1<<<(N_NODES * 32 + 255) / 256, 256>>>(src);

    // ---- layer 2 ----
    k_layer2_z<<<(N_NODES + GT - 1) / GT, 192>>>(W2);
    k_attn2<<<(N_NODES * 3 + 255) / 256, 256>>>(al2, ar2);
    k_remax<<<(N_NODES * 3 + 255) / 256, 256>>>(dst);
    k_logits2<<<(N_EDGES + 255) / 256, 256>>>(src, dst);
    k_agg2<<<(N_NODES * 32 + 255) / 256, 256>>>(src);

    // ---- pool + MLP ----
    {
        int groups = (N_NODES + PNP - 1) / PNP;
        k_pool<<<(groups * 192 + 255) / 256, 256>>>(gid);
    }
    k_mlp<<<N_GRAPHS, 64>>>(d1w, d1b, d2w, d2b, out);
}